// round 15
// baseline (speedup 1.0000x reference)
#include <cuda_runtime.h>
#include <cuda_fp16.h>
#include <math.h>
#include <cstdint>

#define MAXN    6144
#define D       512
#define D4      128
#define INV_PI  0.318309886183790671f

// smem: 2 stages x (128 A rows + 64 B rows) x 144B (128B data + 16B pad)
#define ROWPITCH 144
#define STAGE_BYTES ((128 + 64) * ROWPITCH)     // 27648
#define SMEM_TOTAL (2 * STAGE_BYTES)            // 55296
#define B_OFF (128 * ROWPITCH)

// ---------------- device scratch (allocation-free rule) ----------------
// gathered X fp16: [MAXN][512], row stride 1024 B (tail rows stay zero)
__device__ unsigned char g_ah[MAXN * 1024];
// W fp16: [512][512], row stride 1024 B
__device__ unsigned char g_bh[512 * 1024];

__device__ __forceinline__ uint32_t smem_u32(const void* p) {
    uint32_t a;
    asm("{ .reg .u64 t; cvta.to.shared.u64 t, %1; cvt.u32.u64 %0, t; }"
        : "=r"(a) : "l"(p));
    return a;
}

#define LDM4(r, addr) \
    asm volatile("ldmatrix.sync.aligned.m8n8.x4.shared.b16 {%0,%1,%2,%3}, [%4];" \
        : "=r"((r)[0]), "=r"((r)[1]), "=r"((r)[2]), "=r"((r)[3]) : "r"(addr))

#define MMA16816(c, a, b0, b1) \
    asm volatile("mma.sync.aligned.m16n8k16.row.col.f32.f16.f16.f32 " \
        "{%0,%1,%2,%3}, {%4,%5,%6,%7}, {%8,%9}, {%0,%1,%2,%3};" \
        : "+f"((c)[0]), "+f"((c)[1]), "+f"((c)[2]), "+f"((c)[3]) \
        : "r"((a)[0]), "r"((a)[1]), "r"((a)[2]), "r"((a)[3]), "r"(b0), "r"(b1))

#define CP16(dst, src) \
    asm volatile("cp.async.cg.shared.global [%0], [%1], 16;" :: "r"(dst), "l"(src))
#define CP_COMMIT() asm volatile("cp.async.commit_group;" ::: "memory")
#define CP_WAIT0()  asm volatile("cp.async.wait_group 0;" ::: "memory")

// ---------------------------------------------------------------------------
// Kernel 1: fused chain-find + edge weights + gather + fp16 convert (X),
// and W convert.
// Blocks [0,N): node b. Locate dialog via dia_len prefix (smem), load the
//   dialog's speaker flags (parallel, L2-hit), find prev/next same-speaker
//   neighbors, compute both edge weights from one pass over rows i/p/n,
//   gather, convert to fp16.
// Blocks [N,N+512): W row -> fp16.
// ---------------------------------------------------------------------------
__global__ __launch_bounds__(128)
void split_kernel(const float* __restrict__ inputs,
                  const int* __restrict__ dl,
                  const int* __restrict__ q,
                  const float* __restrict__ Wm,
                  int n_dialogs, int N)
{
    __shared__ int   s_dl[128];
    __shared__ int   s_sp[512];
    __shared__ int   s_q64;
    __shared__ float s_red[5][4];

    int b = blockIdx.x;
    int t = threadIdx.x;   // 0..127

    if (b >= N) {
        int r = b - N;
        float4 w = ((const float4*)(Wm + (size_t)r * D))[t];
        unsigned short hs[4];
        hs[0] = __half_as_ushort(__float2half(w.x));
        hs[1] = __half_as_ushort(__float2half(w.y));
        hs[2] = __half_as_ushort(__float2half(w.z));
        hs[3] = __half_as_ushort(__float2half(w.w));
        uint2 hv = make_uint2((uint32_t)hs[0] | ((uint32_t)hs[1] << 16),
                              (uint32_t)hs[2] | ((uint32_t)hs[3] << 16));
        ((uint2*)(g_bh + (size_t)r * 1024))[t] = hv;
        return;
    }

    // ---- dtype detection (one-hot pairs sum to 1 only in int32 layout) ----
    if (t == 0) s_q64 = 0;
    __syncthreads();
    if (t < 64 && t < N) {
        if (q[2 * t] + q[2 * t + 1] != 1) atomicExch(&s_q64, 1);
    }
    int dstride = (dl[1] == 0) ? 2 : 1;         // lengths positive
    if (t < n_dialogs && t < 128) s_dl[t] = dl[t * dstride];
    __syncthreads();
    int qstride = s_q64 ? 4 : 2;

    // ---- locate dialog containing node b ----
    int start = 0, len = 0;
    {
        int acc = 0;
        for (int dd = 0; dd < n_dialogs; ++dd) {    // smem reads, uniform
            int l = s_dl[dd];
            if (b >= acc && b < acc + l) { start = acc; len = l; break; }
            acc += l;
        }
    }

    // ---- load this dialog's speaker flags ----
    for (int j = t; j < len; j += blockDim.x)
        s_sp[j] = (q[(size_t)(start + j) * qstride] == 1) ? 0 : 1;
    __syncthreads();

    int loc = b - start;
    int s = s_sp[loc];
    int p = -1, nx = -1;
    for (int j = loc - 1; j >= 0; --j)
        if (s_sp[j] == s) { p = start + j; break; }
    for (int j = loc + 1; j < len; ++j)
        if (s_sp[j] == s) { nx = start + j; break; }

    // ---- gather + weights (single pass over i/p/n rows) ----
    const float4* in4 = (const float4*)inputs;
    float4 xi = in4[(size_t)b * D4 + t];
    float4 up = make_float4(0.f, 0.f, 0.f, 0.f);
    float4 un = make_float4(0.f, 0.f, 0.f, 0.f);
    if (p  >= 0) up = in4[(size_t)p  * D4 + t];
    if (nx >= 0) un = in4[(size_t)nx * D4 + t];

    float sm[5];
    sm[0] = xi.x*up.x + xi.y*up.y + xi.z*up.z + xi.w*up.w;
    sm[1] = xi.x*un.x + xi.y*un.y + xi.z*un.z + xi.w*un.w;
    sm[2] = xi.x*xi.x + xi.y*xi.y + xi.z*xi.z + xi.w*xi.w;
    sm[3] = up.x*up.x + up.y*up.y + up.z*up.z + up.w*up.w;
    sm[4] = un.x*un.x + un.y*un.y + un.z*un.z + un.w*un.w;

    int lane = t & 31, warp = t >> 5;
    #pragma unroll
    for (int v = 0; v < 5; ++v) {
        #pragma unroll
        for (int off = 16; off > 0; off >>= 1)
            sm[v] += __shfl_down_sync(0xffffffffu, sm[v], off);
    }
    if (lane == 0) {
        #pragma unroll
        for (int v = 0; v < 5; ++v) s_red[v][warp] = sm[v];
    }
    __syncthreads();
    float dip = s_red[0][0] + s_red[0][1] + s_red[0][2] + s_red[0][3];
    float din = s_red[1][0] + s_red[1][1] + s_red[1][2] + s_red[1][3];
    float nii = s_red[2][0] + s_red[2][1] + s_red[2][2] + s_red[2][3];
    float npp = s_red[3][0] + s_red[3][1] + s_red[3][2] + s_red[3][3];
    float nnn = s_red[4][0] + s_red[4][1] + s_red[4][2] + s_red[4][3];

    float wp = 0.f, wn = 0.f;
    if (p >= 0) {
        float den = sqrtf(nii) * sqrtf(npp);
        float c = (den > 0.f) ? (dip / den) : 0.f;
        c = fminf(1.f, fmaxf(-1.f, c));
        wp = 1.f - acosf(c) * INV_PI;
    }
    if (nx >= 0) {
        float den = sqrtf(nii) * sqrtf(nnn);
        float c = (den > 0.f) ? (din / den) : 0.f;
        c = fminf(1.f, fmaxf(-1.f, c));
        wn = 1.f - acosf(c) * INV_PI;
    }

    float f[4];
    f[0] = xi.x + wp * up.x + wn * un.x;
    f[1] = xi.y + wp * up.y + wn * un.y;
    f[2] = xi.z + wp * up.z + wn * un.z;
    f[3] = xi.w + wp * up.w + wn * un.w;

    unsigned short hs[4];
    #pragma unroll
    for (int j = 0; j < 4; ++j)
        hs[j] = __half_as_ushort(__float2half(f[j]));
    uint2 hv = make_uint2((uint32_t)hs[0] | ((uint32_t)hs[1] << 16),
                          (uint32_t)hs[2] | ((uint32_t)hs[3] << 16));
    ((uint2*)(g_ah + (size_t)b * 1024))[t] = hv;
}

// ---------------------------------------------------------------------------
// Kernel 2: HMMA GEMM  out[N,512] = fp16(x_gathered) x fp16(W)^T + bias
// fp32 accumulate, K=512 (8 iters of BK=64). Block 128x64, 256 threads =
// 8 warps of 32x32 tiles, cp.async double-buffered smem, occ 3, 376 CTAs.
// ---------------------------------------------------------------------------
__global__ __launch_bounds__(256, 3)
void gemm_mma(const float* __restrict__ bias, float* __restrict__ out, int N)
{
    extern __shared__ __align__(16) unsigned char smem[];

    int t = threadIdx.x;
    int m0 = blockIdx.x * 128;
    int n0 = blockIdx.y * 64;
    int lane = t & 31, w = t >> 5;
    int wm = w >> 1;           // 0..3 -> 32-row group
    int wn = w & 1;            // 0..1 -> 32-col group

    uint32_t sbase = smem_u32(smem);
    uint32_t stg[2] = { sbase, sbase + STAGE_BYTES };

    int ar[4], ac[4], br[2], bc[2];
    #pragma unroll
    for (int j = 0; j < 4; ++j) {
        int c = t + j * 256;
        ar[j] = c >> 3; ac[j] = c & 7;
    }
    #pragma unroll
    for (int j = 0; j < 2; ++j) {
        int c = t + j * 256;
        br[j] = c >> 3; bc[j] = c & 7;
    }

    uint32_t a_ld = (uint32_t)(wm * 32 + (lane & 15)) * ROWPITCH + ((lane >> 4) * 16);
    uint32_t b_ld = (uint32_t)(B_OFF + (wn * 32 + (lane & 15)) * ROWPITCH) + ((lane >> 4) * 16);

    float acc[2][4][4];
    #pragma unroll
    for (int i = 0; i < 2; ++i)
        #pragma unroll
        for (int j = 0; j < 4; ++j)
            #pragma unroll
            for (int r = 0; r < 4; ++r) acc[i][j][r] = 0.f;

    auto issue = [&](int it, int buf) {
        int off = it * 128;                 // 64 fp16 = 128 B per iter
        uint32_t s = stg[buf];
        #pragma unroll
        for (int j = 0; j < 4; ++j)
            CP16(s + ar[j] * ROWPITCH + ac[j] * 16,
                 g_ah + (size_t)(m0 + ar[j]) * 1024 + off + ac[j] * 16);
        #pragma unroll
        for (int j = 0; j < 2; ++j)
            CP16(s + B_OFF + br[j] * ROWPITCH + bc[j] * 16,
                 g_bh + (size_t)(n0 + br[j]) * 1024 + off + bc[j] * 16);
        CP_COMMIT();
    };

    issue(0, 0);

    #pragma unroll 1
    for (int it = 0; it < 8; ++it) {
        int buf = it & 1;
        CP_WAIT0();
        __syncthreads();
        if (it < 7) issue(it + 1, buf ^ 1);

        uint32_t ab = stg[buf] + a_ld;
        uint32_t bb = stg[buf] + b_ld;
        #pragma unroll
        for (int kk = 0; kk < 4; ++kk) {
            uint32_t A0[4], A1[4], B0[4], B1[4];
            LDM4(A0, ab + kk * 32);
            LDM4(A1, ab + 16 * ROWPITCH + kk * 32);
            LDM4(B0, bb + kk * 32);
            LDM4(B1, bb + 16 * ROWPITCH + kk * 32);
            MMA16816(acc[0][0], A0, B0[0], B0[2]);
            MMA16816(acc[0][1], A0, B0[1], B0[3]);
            MMA16816(acc[0][2], A0, B1[0], B1[2]);
            MMA16816(acc[0][3], A0, B1[1], B1[3]);
            MMA16816(acc[1][0], A1, B0[0], B0[2]);
            MMA16816(acc[1][1], A1, B0[1], B0[3]);
            MMA16816(acc[1][2], A1, B1[0], B1[2]);
            MMA16816(acc[1][3], A1, B1[1], B1[3]);
        }
    }

    // ---- epilogue: add bias, store out ----
    int r0 = m0 + wm * 32 + (lane >> 2);
    int cb = n0 + wn * 32 + (lane & 3) * 2;
    #pragma unroll
    for (int mi = 0; mi < 2; ++mi) {
        int row = r0 + mi * 16;
        #pragma unroll
        for (int nj = 0; nj < 4; ++nj) {
            int col = cb + nj * 8;
            float b0 = __ldg(bias + col);
            float b1 = __ldg(bias + col + 1);
            if (row < N)
                *(float2*)(out + (size_t)row * D + col) =
                    make_float2(acc[mi][nj][0] + b0, acc[mi][nj][1] + b1);
            if (row + 8 < N)
                *(float2*)(out + (size_t)(row + 8) * D + col) =
                    make_float2(acc[mi][nj][2] + b0, acc[mi][nj][3] + b1);
        }
    }
}

// ---------------------------------------------------------------------------
extern "C" void kernel_launch(void* const* d_in, const int* in_sizes, int n_in,
                              void* d_out, int out_size)
{
    const float* inputs  = (const float*)d_in[0];
    const int*   dia_len = (const int*)d_in[1];
    const int*   qmask   = (const int*)d_in[2];
    const float* Wm      = (const float*)d_in[3];
    const float* bias    = (const float*)d_in[4];
    float*       out     = (float*)d_out;

    int N  = in_sizes[0] / D;      // 6000
    int nd = in_sizes[1];
    if (nd > 128) nd = 128;        // s_dl capacity; dataset has 60

    static bool attr_done = false;
    if (!attr_done) {
        cudaFuncSetAttribute(gemm_mma, cudaFuncAttributeMaxDynamicSharedMemorySize,
                             SMEM_TOTAL);
        attr_done = true;
    }

    split_kernel<<<N + 512, 128>>>(inputs, dia_len, qmask, Wm, nd, N);

    dim3 grid((N + 127) / 128, D / 64);
    gemm_mma<<<grid, 256, SMEM_TOTAL>>>(bias, out, N);
}

// round 16
// speedup vs baseline: 1.0094x; 1.0094x over previous
#include <cuda_runtime.h>
#include <cuda_fp16.h>
#include <math.h>
#include <cstdint>

#define MAXN    6144
#define D       512
#define D4      128
#define INV_PI  0.318309886183790671f

// smem: 2 stages x (128 A rows + 64 B rows) x 144B (128B data + 16B pad)
#define ROWPITCH 144
#define STAGE_BYTES ((128 + 64) * ROWPITCH)     // 27648
#define SMEM_TOTAL (2 * STAGE_BYTES)            // 55296
#define B_OFF (128 * ROWPITCH)

// ---------------- device scratch (allocation-free rule) ----------------
// gathered X fp16: [MAXN][512], row stride 1024 B (tail rows stay zero)
__device__ unsigned char g_ah[MAXN * 1024];
// W fp16: [512][512], row stride 1024 B
__device__ unsigned char g_bh[512 * 1024];

__device__ __forceinline__ uint32_t smem_u32(const void* p) {
    uint32_t a;
    asm("{ .reg .u64 t; cvta.to.shared.u64 t, %1; cvt.u32.u64 %0, t; }"
        : "=r"(a) : "l"(p));
    return a;
}

#define LDM4(r, addr) \
    asm volatile("ldmatrix.sync.aligned.m8n8.x4.shared.b16 {%0,%1,%2,%3}, [%4];" \
        : "=r"((r)[0]), "=r"((r)[1]), "=r"((r)[2]), "=r"((r)[3]) : "r"(addr))

#define MMA16816(c, a, b0, b1) \
    asm volatile("mma.sync.aligned.m16n8k16.row.col.f32.f16.f16.f32 " \
        "{%0,%1,%2,%3}, {%4,%5,%6,%7}, {%8,%9}, {%0,%1,%2,%3};" \
        : "+f"((c)[0]), "+f"((c)[1]), "+f"((c)[2]), "+f"((c)[3]) \
        : "r"((a)[0]), "r"((a)[1]), "r"((a)[2]), "r"((a)[3]), "r"(b0), "r"(b1))

#define CP16(dst, src) \
    asm volatile("cp.async.cg.shared.global [%0], [%1], 16;" :: "r"(dst), "l"(src))
#define CP_COMMIT() asm volatile("cp.async.commit_group;" ::: "memory")
#define CP_WAIT0()  asm volatile("cp.async.wait_group 0;" ::: "memory")

// ---------------------------------------------------------------------------
// Kernel 1: fused neighbor-find (ballot window) + edge weights + gather +
// fp16 convert (X), and W convert.
// Blocks [0,N): node b. Dialog bounds from 60-entry smem scan; prev/next
//   same-speaker neighbor via one parallel 32-probe window per direction
//   (__ballot_sync), serial fallback for >32-runs. Then one pass over rows
//   i/p/n: 5 reductions -> both edge weights -> gather -> fp16.
// Blocks [N,N+512): W row -> fp16.
// ---------------------------------------------------------------------------
__global__ __launch_bounds__(128)
void split_kernel(const float* __restrict__ inputs,
                  const int* __restrict__ dl,
                  const int* __restrict__ q,
                  const float* __restrict__ Wm,
                  int n_dialogs, int N)
{
    __shared__ int   s_dl[128];
    __shared__ int   s_q64;
    __shared__ int   s_pn[2];
    __shared__ float s_red[5][4];

    int b = blockIdx.x;
    int t = threadIdx.x;   // 0..127

    if (b >= N) {
        int r = b - N;
        float4 w = ((const float4*)(Wm + (size_t)r * D))[t];
        unsigned short hs[4];
        hs[0] = __half_as_ushort(__float2half(w.x));
        hs[1] = __half_as_ushort(__float2half(w.y));
        hs[2] = __half_as_ushort(__float2half(w.z));
        hs[3] = __half_as_ushort(__float2half(w.w));
        uint2 hv = make_uint2((uint32_t)hs[0] | ((uint32_t)hs[1] << 16),
                              (uint32_t)hs[2] | ((uint32_t)hs[3] << 16));
        ((uint2*)(g_bh + (size_t)r * 1024))[t] = hv;
        return;
    }

    // ---- dtype detection (one-hot pairs sum to 1 only in int32 layout) ----
    if (t == 0) s_q64 = 0;
    __syncthreads();
    if (t < 64 && t < N) {
        if (q[2 * t] + q[2 * t + 1] != 1) atomicExch(&s_q64, 1);
    }
    int dstride = (dl[1] == 0) ? 2 : 1;         // lengths positive
    if (t < n_dialogs && t < 128) s_dl[t] = dl[t * dstride];
    __syncthreads();
    int qstride = s_q64 ? 4 : 2;

    // ---- locate dialog containing node b (uniform smem scan) ----
    int start = 0, len = 0;
    {
        int acc = 0;
        for (int dd = 0; dd < n_dialogs; ++dd) {
            int l = s_dl[dd];
            if (b >= acc && b < acc + l) { start = acc; len = l; break; }
            acc += l;
        }
    }
    int loc = b - start;

    // speaker flag accessor (dialog-local index)
    auto flag = [&](int j) -> int {
        return (q[(size_t)(start + j) * qstride] == 1) ? 0 : 1;
    };

    int lane = t & 31, warp = t >> 5;

    // ---- parallel neighbor probes ----
    if (warp == 0) {                       // prev: loc-1 .. loc-32
        int s0 = flag(loc);                // broadcast load (same addr)
        int j = loc - 1 - lane;
        int m = (j >= 0 && flag(j) == s0) ? 1 : 0;
        unsigned bal = __ballot_sync(0xffffffffu, m);
        if (lane == 0) {
            int p = -1;
            if (bal) p = start + loc - (__ffs(bal));
            else if (loc - 33 >= 0) {      // rare fallback (>32 run)
                for (int jj = loc - 33; jj >= 0; --jj)
                    if (flag(jj) == s0) { p = start + jj; break; }
            }
            s_pn[0] = p;
        }
    } else if (warp == 1) {                // next: loc+1 .. loc+32
        int s0 = flag(loc);
        int j = loc + 1 + lane;
        int m = (j < len && flag(j) == s0) ? 1 : 0;
        unsigned bal = __ballot_sync(0xffffffffu, m);
        if (lane == 0) {
            int nx = -1;
            if (bal) nx = start + loc + (__ffs(bal));
            else if (loc + 33 < len) {
                for (int jj = loc + 33; jj < len; ++jj)
                    if (flag(jj) == s0) { nx = start + jj; break; }
            }
            s_pn[1] = nx;
        }
    }
    __syncthreads();
    int p  = s_pn[0];
    int nx = s_pn[1];

    // ---- gather + weights (single pass over i/p/n rows) ----
    const float4* in4 = (const float4*)inputs;
    float4 xi = in4[(size_t)b * D4 + t];
    float4 up = make_float4(0.f, 0.f, 0.f, 0.f);
    float4 un = make_float4(0.f, 0.f, 0.f, 0.f);
    if (p  >= 0) up = in4[(size_t)p  * D4 + t];
    if (nx >= 0) un = in4[(size_t)nx * D4 + t];

    float sm[5];
    sm[0] = xi.x*up.x + xi.y*up.y + xi.z*up.z + xi.w*up.w;
    sm[1] = xi.x*un.x + xi.y*un.y + xi.z*un.z + xi.w*un.w;
    sm[2] = xi.x*xi.x + xi.y*xi.y + xi.z*xi.z + xi.w*xi.w;
    sm[3] = up.x*up.x + up.y*up.y + up.z*up.z + up.w*up.w;
    sm[4] = un.x*un.x + un.y*un.y + un.z*un.z + un.w*un.w;

    #pragma unroll
    for (int v = 0; v < 5; ++v) {
        #pragma unroll
        for (int off = 16; off > 0; off >>= 1)
            sm[v] += __shfl_down_sync(0xffffffffu, sm[v], off);
    }
    if (lane == 0) {
        #pragma unroll
        for (int v = 0; v < 5; ++v) s_red[v][warp] = sm[v];
    }
    __syncthreads();
    float dip = s_red[0][0] + s_red[0][1] + s_red[0][2] + s_red[0][3];
    float din = s_red[1][0] + s_red[1][1] + s_red[1][2] + s_red[1][3];
    float nii = s_red[2][0] + s_red[2][1] + s_red[2][2] + s_red[2][3];
    float npp = s_red[3][0] + s_red[3][1] + s_red[3][2] + s_red[3][3];
    float nnn = s_red[4][0] + s_red[4][1] + s_red[4][2] + s_red[4][3];

    float wp = 0.f, wn = 0.f;
    if (p >= 0) {
        float den = sqrtf(nii) * sqrtf(npp);
        float c = (den > 0.f) ? (dip / den) : 0.f;
        c = fminf(1.f, fmaxf(-1.f, c));
        wp = 1.f - acosf(c) * INV_PI;
    }
    if (nx >= 0) {
        float den = sqrtf(nii) * sqrtf(nnn);
        float c = (den > 0.f) ? (din / den) : 0.f;
        c = fminf(1.f, fmaxf(-1.f, c));
        wn = 1.f - acosf(c) * INV_PI;
    }

    float f[4];
    f[0] = xi.x + wp * up.x + wn * un.x;
    f[1] = xi.y + wp * up.y + wn * un.y;
    f[2] = xi.z + wp * up.z + wn * un.z;
    f[3] = xi.w + wp * up.w + wn * un.w;

    unsigned short hs[4];
    #pragma unroll
    for (int j = 0; j < 4; ++j)
        hs[j] = __half_as_ushort(__float2half(f[j]));
    uint2 hv = make_uint2((uint32_t)hs[0] | ((uint32_t)hs[1] << 16),
                          (uint32_t)hs[2] | ((uint32_t)hs[3] << 16));
    ((uint2*)(g_ah + (size_t)b * 1024))[t] = hv;
}

// ---------------------------------------------------------------------------
// Kernel 2: HMMA GEMM  out[N,512] = fp16(x_gathered) x fp16(W)^T + bias
// fp32 accumulate, K=512 (8 iters of BK=64). Block 128x64, 256 threads =
// 8 warps of 32x32 tiles, cp.async double-buffered smem, occ 3, 376 CTAs.
// ---------------------------------------------------------------------------
__global__ __launch_bounds__(256, 3)
void gemm_mma(const float* __restrict__ bias, float* __restrict__ out, int N)
{
    extern __shared__ __align__(16) unsigned char smem[];

    int t = threadIdx.x;
    int m0 = blockIdx.x * 128;
    int n0 = blockIdx.y * 64;
    int lane = t & 31, w = t >> 5;
    int wm = w >> 1;           // 0..3 -> 32-row group
    int wn = w & 1;            // 0..1 -> 32-col group

    uint32_t sbase = smem_u32(smem);
    uint32_t stg[2] = { sbase, sbase + STAGE_BYTES };

    int ar[4], ac[4], br[2], bc[2];
    #pragma unroll
    for (int j = 0; j < 4; ++j) {
        int c = t + j * 256;
        ar[j] = c >> 3; ac[j] = c & 7;
    }
    #pragma unroll
    for (int j = 0; j < 2; ++j) {
        int c = t + j * 256;
        br[j] = c >> 3; bc[j] = c & 7;
    }

    uint32_t a_ld = (uint32_t)(wm * 32 + (lane & 15)) * ROWPITCH + ((lane >> 4) * 16);
    uint32_t b_ld = (uint32_t)(B_OFF + (wn * 32 + (lane & 15)) * ROWPITCH) + ((lane >> 4) * 16);

    float acc[2][4][4];
    #pragma unroll
    for (int i = 0; i < 2; ++i)
        #pragma unroll
        for (int j = 0; j < 4; ++j)
            #pragma unroll
            for (int r = 0; r < 4; ++r) acc[i][j][r] = 0.f;

    auto issue = [&](int it, int buf) {
        int off = it * 128;                 // 64 fp16 = 128 B per iter
        uint32_t s = stg[buf];
        #pragma unroll
        for (int j = 0; j < 4; ++j)
            CP16(s + ar[j] * ROWPITCH + ac[j] * 16,
                 g_ah + (size_t)(m0 + ar[j]) * 1024 + off + ac[j] * 16);
        #pragma unroll
        for (int j = 0; j < 2; ++j)
            CP16(s + B_OFF + br[j] * ROWPITCH + bc[j] * 16,
                 g_bh + (size_t)(n0 + br[j]) * 1024 + off + bc[j] * 16);
        CP_COMMIT();
    };

    issue(0, 0);

    #pragma unroll 1
    for (int it = 0; it < 8; ++it) {
        int buf = it & 1;
        CP_WAIT0();
        __syncthreads();
        if (it < 7) issue(it + 1, buf ^ 1);

        uint32_t ab = stg[buf] + a_ld;
        uint32_t bb = stg[buf] + b_ld;
        #pragma unroll
        for (int kk = 0; kk < 4; ++kk) {
            uint32_t A0[4], A1[4], B0[4], B1[4];
            LDM4(A0, ab + kk * 32);
            LDM4(A1, ab + 16 * ROWPITCH + kk * 32);
            LDM4(B0, bb + kk * 32);
            LDM4(B1, bb + 16 * ROWPITCH + kk * 32);
            MMA16816(acc[0][0], A0, B0[0], B0[2]);
            MMA16816(acc[0][1], A0, B0[1], B0[3]);
            MMA16816(acc[0][2], A0, B1[0], B1[2]);
            MMA16816(acc[0][3], A0, B1[1], B1[3]);
            MMA16816(acc[1][0], A1, B0[0], B0[2]);
            MMA16816(acc[1][1], A1, B0[1], B0[3]);
            MMA16816(acc[1][2], A1, B1[0], B1[2]);
            MMA16816(acc[1][3], A1, B1[1], B1[3]);
        }
    }

    // ---- epilogue: add bias, store out ----
    int r0 = m0 + wm * 32 + (lane >> 2);
    int cb = n0 + wn * 32 + (lane & 3) * 2;
    #pragma unroll
    for (int mi = 0; mi < 2; ++mi) {
        int row = r0 + mi * 16;
        #pragma unroll
        for (int nj = 0; nj < 4; ++nj) {
            int col = cb + nj * 8;
            float b0 = __ldg(bias + col);
            float b1 = __ldg(bias + col + 1);
            if (row < N)
                *(float2*)(out + (size_t)row * D + col) =
                    make_float2(acc[mi][nj][0] + b0, acc[mi][nj][1] + b1);
            if (row + 8 < N)
                *(float2*)(out + (size_t)(row + 8) * D + col) =
                    make_float2(acc[mi][nj][2] + b0, acc[mi][nj][3] + b1);
        }
    }
}

// ---------------------------------------------------------------------------
extern "C" void kernel_launch(void* const* d_in, const int* in_sizes, int n_in,
                              void* d_out, int out_size)
{
    const float* inputs  = (const float*)d_in[0];
    const int*   dia_len = (const int*)d_in[1];
    const int*   qmask   = (const int*)d_in[2];
    const float* Wm      = (const float*)d_in[3];
    const float* bias    = (const float*)d_in[4];
    float*       out     = (float*)d_out;

    int N  = in_sizes[0] / D;      // 6000
    int nd = in_sizes[1];
    if (nd > 128) nd = 128;        // s_dl capacity; dataset has 60

    static bool attr_done = false;
    if (!attr_done) {
        cudaFuncSetAttribute(gemm_mma, cudaFuncAttributeMaxDynamicSharedMemorySize,
                             SMEM_TOTAL);
        attr_done = true;
    }

    split_kernel<<<N + 512, 128>>>(inputs, dia_len, qmask, Wm, nd, N);

    dim3 grid((N + 127) / 128, D / 64);
    gemm_mma<<<grid, 256, SMEM_TOTAL>>>(bias, out, N);
}

// round 17
// speedup vs baseline: 1.2092x; 1.1979x over previous
#include <cuda_runtime.h>
#include <cuda_fp16.h>
#include <math.h>
#include <cstdint>

#define MAXN    6144
#define D       512
#define D4      128
#define INV_PI  0.318309886183790671f

// smem: 2 stages x (128 A rows + 64 B rows) x 144B (128B data + 16B pad)
#define ROWPITCH 144
#define STAGE_BYTES ((128 + 64) * ROWPITCH)     // 27648
#define SMEM_TOTAL (2 * STAGE_BYTES)            // 55296
#define B_OFF (128 * ROWPITCH)

// ---------------- device scratch (allocation-free rule) ----------------
__device__ int   g_prev[MAXN];
__device__ int   g_next[MAXN];
// gathered X fp16: [MAXN][512], row stride 1024 B (tail rows stay zero)
__device__ unsigned char g_ah[MAXN * 1024];
// W fp16: [512][512], row stride 1024 B
__device__ unsigned char g_bh[512 * 1024];

__device__ __forceinline__ uint32_t smem_u32(const void* p) {
    uint32_t a;
    asm("{ .reg .u64 t; cvta.to.shared.u64 t, %1; cvt.u32.u64 %0, t; }"
        : "=r"(a) : "l"(p));
    return a;
}

#define LDM4(r, addr) \
    asm volatile("ldmatrix.sync.aligned.m8n8.x4.shared.b16 {%0,%1,%2,%3}, [%4];" \
        : "=r"((r)[0]), "=r"((r)[1]), "=r"((r)[2]), "=r"((r)[3]) : "r"(addr))

#define MMA16816(c, a, b0, b1) \
    asm volatile("mma.sync.aligned.m16n8k16.row.col.f32.f16.f16.f32 " \
        "{%0,%1,%2,%3}, {%4,%5,%6,%7}, {%8,%9}, {%0,%1,%2,%3};" \
        : "+f"((c)[0]), "+f"((c)[1]), "+f"((c)[2]), "+f"((c)[3]) \
        : "r"((a)[0]), "r"((a)[1]), "r"((a)[2]), "r"((a)[3]), "r"(b0), "r"(b1))

#define CP16(dst, src) \
    asm volatile("cp.async.cg.shared.global [%0], [%1], 16;" :: "r"(dst), "l"(src))
#define CP_COMMIT() asm volatile("cp.async.commit_group;" ::: "memory")
#define CP_WAIT0()  asm volatile("cp.async.wait_group 0;" ::: "memory")

// ---------------------------------------------------------------------------
// Kernel 1: blocks [0, nd): per-dialog prev/next chains (parallel smem scan).
//           blocks [nd, nd+512): W row -> fp16 (independent; fills idle SMs).
// ---------------------------------------------------------------------------
__global__ __launch_bounds__(128)
void prep_kernel(const int* __restrict__ dl,
                 const int* __restrict__ q,
                 const float* __restrict__ Wm,
                 int n_dialogs, int N)
{
    __shared__ int s_dl[512];
    __shared__ int s_sp[512];
    __shared__ int s_q64;

    int blk = blockIdx.x;
    int tid = threadIdx.x;

    if (blk >= n_dialogs) {
        // ---- W conversion block ----
        int r = blk - n_dialogs;          // 0..511
        float4 w = ((const float4*)(Wm + (size_t)r * D))[tid];
        unsigned short hs[4];
        hs[0] = __half_as_ushort(__float2half(w.x));
        hs[1] = __half_as_ushort(__float2half(w.y));
        hs[2] = __half_as_ushort(__float2half(w.z));
        hs[3] = __half_as_ushort(__float2half(w.w));
        uint2 hv = make_uint2((uint32_t)hs[0] | ((uint32_t)hs[1] << 16),
                              (uint32_t)hs[2] | ((uint32_t)hs[3] << 16));
        ((uint2*)(g_bh + (size_t)r * 1024))[tid] = hv;
        return;
    }

    int d = blk;

    if (tid == 0) s_q64 = 0;
    __syncthreads();
    // int64-as-int32 detection: one-hot pairs sum to 1 only in int32 layout.
    if (tid < 64 && tid < N) {
        if (q[2 * tid] + q[2 * tid + 1] != 1) atomicExch(&s_q64, 1);
    }
    int dstride = (dl[1] == 0) ? 2 : 1;          // lengths positive
    for (int t = tid; t < n_dialogs && t < 512; t += blockDim.x)
        s_dl[t] = dl[t * dstride];
    __syncthreads();
    int qstride = s_q64 ? 4 : 2;

    int start = 0;
    for (int t = 0; t < d; ++t) start += s_dl[t];
    int len = s_dl[d];

    for (int t = tid; t < len; t += blockDim.x)
        s_sp[t] = (q[(size_t)(start + t) * qstride] == 1) ? 0 : 1;
    __syncthreads();

    for (int t = tid; t < len; t += blockDim.x) {
        int s = s_sp[t];
        int pv = -1, nx = -1;
        for (int j = t - 1; j >= 0; --j)
            if (s_sp[j] == s) { pv = start + j; break; }
        for (int j = t + 1; j < len; ++j)
            if (s_sp[j] == s) { nx = start + j; break; }
        g_prev[start + t] = pv;
        g_next[start + t] = nx;
    }
}

// ---------------------------------------------------------------------------
// Kernel 2: fused edge weights + gather + fp16 convert (X rows only).
// One block per node; single pass over rows i/p/n computes the 5 reductions,
// both edge weights, the gather, and the fp16 conversion.
// ---------------------------------------------------------------------------
__global__ __launch_bounds__(128)
void split_kernel(const float* __restrict__ inputs, int N)
{
    __shared__ float s_red[5][4];

    int b = blockIdx.x;
    if (b >= N) return;
    int t = threadIdx.x;   // 0..127

    const float4* in4 = (const float4*)inputs;
    int p  = g_prev[b];
    int nx = g_next[b];

    float4 xi = in4[(size_t)b * D4 + t];
    float4 up = make_float4(0.f, 0.f, 0.f, 0.f);
    float4 un = make_float4(0.f, 0.f, 0.f, 0.f);
    if (p  >= 0) up = in4[(size_t)p  * D4 + t];
    if (nx >= 0) un = in4[(size_t)nx * D4 + t];

    float sm[5];
    sm[0] = xi.x*up.x + xi.y*up.y + xi.z*up.z + xi.w*up.w;
    sm[1] = xi.x*un.x + xi.y*un.y + xi.z*un.z + xi.w*un.w;
    sm[2] = xi.x*xi.x + xi.y*xi.y + xi.z*xi.z + xi.w*xi.w;
    sm[3] = up.x*up.x + up.y*up.y + up.z*up.z + up.w*up.w;
    sm[4] = un.x*un.x + un.y*un.y + un.z*un.z + un.w*un.w;

    int lane = t & 31, warp = t >> 5;
    #pragma unroll
    for (int v = 0; v < 5; ++v) {
        #pragma unroll
        for (int off = 16; off > 0; off >>= 1)
            sm[v] += __shfl_down_sync(0xffffffffu, sm[v], off);
    }
    if (lane == 0) {
        #pragma unroll
        for (int v = 0; v < 5; ++v) s_red[v][warp] = sm[v];
    }
    __syncthreads();
    float dip = s_red[0][0] + s_red[0][1] + s_red[0][2] + s_red[0][3];
    float din = s_red[1][0] + s_red[1][1] + s_red[1][2] + s_red[1][3];
    float nii = s_red[2][0] + s_red[2][1] + s_red[2][2] + s_red[2][3];
    float npp = s_red[3][0] + s_red[3][1] + s_red[3][2] + s_red[3][3];
    float nnn = s_red[4][0] + s_red[4][1] + s_red[4][2] + s_red[4][3];

    float wp = 0.f, wn = 0.f;
    if (p >= 0) {
        float den = sqrtf(nii) * sqrtf(npp);
        float c = (den > 0.f) ? (dip / den) : 0.f;
        c = fminf(1.f, fmaxf(-1.f, c));
        wp = 1.f - acosf(c) * INV_PI;
    }
    if (nx >= 0) {
        float den = sqrtf(nii) * sqrtf(nnn);
        float c = (den > 0.f) ? (din / den) : 0.f;
        c = fminf(1.f, fmaxf(-1.f, c));
        wn = 1.f - acosf(c) * INV_PI;
    }

    float f[4];
    f[0] = xi.x + wp * up.x + wn * un.x;
    f[1] = xi.y + wp * up.y + wn * un.y;
    f[2] = xi.z + wp * up.z + wn * un.z;
    f[3] = xi.w + wp * up.w + wn * un.w;

    unsigned short hs[4];
    #pragma unroll
    for (int j = 0; j < 4; ++j)
        hs[j] = __half_as_ushort(__float2half(f[j]));
    uint2 hv = make_uint2((uint32_t)hs[0] | ((uint32_t)hs[1] << 16),
                          (uint32_t)hs[2] | ((uint32_t)hs[3] << 16));
    ((uint2*)(g_ah + (size_t)b * 1024))[t] = hv;
}

// ---------------------------------------------------------------------------
// Kernel 3: HMMA GEMM  out[N,512] = fp16(x_gathered) x fp16(W)^T + bias
// fp32 accumulate, K=512 (8 iters of BK=64). Block 128x64, 256 threads =
// 8 warps of 32x32 tiles, cp.async double-buffered smem, occ 3, 376 CTAs.
// (measured at the mma.sync quarter-rate roofline; do not disturb)
// ---------------------------------------------------------------------------
__global__ __launch_bounds__(256, 3)
void gemm_mma(const float* __restrict__ bias, float* __restrict__ out, int N)
{
    extern __shared__ __align__(16) unsigned char smem[];

    int t = threadIdx.x;
    int m0 = blockIdx.x * 128;
    int n0 = blockIdx.y * 64;
    int lane = t & 31, w = t >> 5;
    int wm = w >> 1;           // 0..3 -> 32-row group
    int wn = w & 1;            // 0..1 -> 32-col group

    uint32_t sbase = smem_u32(smem);
    uint32_t stg[2] = { sbase, sbase + STAGE_BYTES };

    int ar[4], ac[4], br[2], bc[2];
    #pragma unroll
    for (int j = 0; j < 4; ++j) {
        int c = t + j * 256;
        ar[j] = c >> 3; ac[j] = c & 7;
    }
    #pragma unroll
    for (int j = 0; j < 2; ++j) {
        int c = t + j * 256;
        br[j] = c >> 3; bc[j] = c & 7;
    }

    uint32_t a_ld = (uint32_t)(wm * 32 + (lane & 15)) * ROWPITCH + ((lane >> 4) * 16);
    uint32_t b_ld = (uint32_t)(B_OFF + (wn * 32 + (lane & 15)) * ROWPITCH) + ((lane >> 4) * 16);

    float acc[2][4][4];
    #pragma unroll
    for (int i = 0; i < 2; ++i)
        #pragma unroll
        for (int j = 0; j < 4; ++j)
            #pragma unroll
            for (int r = 0; r < 4; ++r) acc[i][j][r] = 0.f;

    auto issue = [&](int it, int buf) {
        int off = it * 128;                 // 64 fp16 = 128 B per iter
        uint32_t s = stg[buf];
        #pragma unroll
        for (int j = 0; j < 4; ++j)
            CP16(s + ar[j] * ROWPITCH + ac[j] * 16,
                 g_ah + (size_t)(m0 + ar[j]) * 1024 + off + ac[j] * 16);
        #pragma unroll
        for (int j = 0; j < 2; ++j)
            CP16(s + B_OFF + br[j] * ROWPITCH + bc[j] * 16,
                 g_bh + (size_t)(n0 + br[j]) * 1024 + off + bc[j] * 16);
        CP_COMMIT();
    };

    issue(0, 0);

    #pragma unroll 1
    for (int it = 0; it < 8; ++it) {
        int buf = it & 1;
        CP_WAIT0();
        __syncthreads();
        if (it < 7) issue(it + 1, buf ^ 1);

        uint32_t ab = stg[buf] + a_ld;
        uint32_t bb = stg[buf] + b_ld;
        #pragma unroll
        for (int kk = 0; kk < 4; ++kk) {
            uint32_t A0[4], A1[4], B0[4], B1[4];
            LDM4(A0, ab + kk * 32);
            LDM4(A1, ab + 16 * ROWPITCH + kk * 32);
            LDM4(B0, bb + kk * 32);
            LDM4(B1, bb + 16 * ROWPITCH + kk * 32);
            MMA16816(acc[0][0], A0, B0[0], B0[2]);
            MMA16816(acc[0][1], A0, B0[1], B0[3]);
            MMA16816(acc[0][2], A0, B1[0], B1[2]);
            MMA16816(acc[0][3], A0, B1[1], B1[3]);
            MMA16816(acc[1][0], A1, B0[0], B0[2]);
            MMA16816(acc[1][1], A1, B0[1], B0[3]);
            MMA16816(acc[1][2], A1, B1[0], B1[2]);
            MMA16816(acc[1][3], A1, B1[1], B1[3]);
        }
    }

    // ---- epilogue: add bias, store out ----
    int r0 = m0 + wm * 32 + (lane >> 2);
    int cb = n0 + wn * 32 + (lane & 3) * 2;
    #pragma unroll
    for (int mi = 0; mi < 2; ++mi) {
        int row = r0 + mi * 16;
        #pragma unroll
        for (int nj = 0; nj < 4; ++nj) {
            int col = cb + nj * 8;
            float b0 = __ldg(bias + col);
            float b1 = __ldg(bias + col + 1);
            if (row < N)
                *(float2*)(out + (size_t)row * D + col) =
                    make_float2(acc[mi][nj][0] + b0, acc[mi][nj][1] + b1);
            if (row + 8 < N)
                *(float2*)(out + (size_t)(row + 8) * D + col) =
                    make_float2(acc[mi][nj][2] + b0, acc[mi][nj][3] + b1);
        }
    }
}

// ---------------------------------------------------------------------------
extern "C" void kernel_launch(void* const* d_in, const int* in_sizes, int n_in,
                              void* d_out, int out_size)
{
    const float* inputs  = (const float*)d_in[0];
    const int*   dia_len = (const int*)d_in[1];
    const int*   qmask   = (const int*)d_in[2];
    const float* Wm      = (const float*)d_in[3];
    const float* bias    = (const float*)d_in[4];
    float*       out     = (float*)d_out;

    int N  = in_sizes[0] / D;      // 6000
    int nd = in_sizes[1];
    if (nd > 512) nd = 512;        // s_dl capacity; dataset has 60

    static bool attr_done = false;
    if (!attr_done) {
        cudaFuncSetAttribute(gemm_mma, cudaFuncAttributeMaxDynamicSharedMemorySize,
                             SMEM_TOTAL);
        attr_done = true;
    }

    prep_kernel<<<nd + 512, 128>>>(dia_len, qmask, Wm, nd, N);
    split_kernel<<<N, 128>>>(inputs, N);

    dim3 grid((N + 127) / 128, D / 64);
    gemm_mma<<<grid, 256, SMEM_TOTAL>>>(bias, out, N);
}